// round 8
// baseline (speedup 1.0000x reference)
#include <cuda_runtime.h>
#include <cstdint>

#define N_NODES 50000
#define DEG     32
#define HEADS   4
#define OUT_F   16
#define IN_F    64
#define EDIM    (HEADS * OUT_F)   // 64 combined (h,o) features
#define PT_NODES 128              // nodes per proj block

typedef unsigned long long ull;

// Scratch: projected queries/keys, node-major (256B contiguous per node).
__device__ __align__(16) float g_Qf[N_NODES * EDIM];
__device__ __align__(16) float g_Kf[N_NODES * EDIM];

// ---------------------------------------------------------------------------
// f32x2 packed helpers (sm_103a)
// ---------------------------------------------------------------------------
__device__ __forceinline__ ull pack2(float a, float b) {
    ull r; asm("mov.b64 %0, {%1, %2};" : "=l"(r) : "f"(a), "f"(b)); return r;
}
__device__ __forceinline__ float2 unpack2(ull v) {
    float2 r; asm("mov.b64 {%0, %1}, %2;" : "=f"(r.x), "=f"(r.y) : "l"(v)); return r;
}
__device__ __forceinline__ void fma2(ull& d, ull a, ull b) {
    asm("fma.rn.f32x2 %0, %1, %2, %0;" : "+l"(d) : "l"(a), "l"(b));
}
__device__ __forceinline__ ull add2(ull a, ull b) {
    ull r; asm("add.rn.f32x2 %0, %1, %2;" : "=l"(r) : "l"(a), "l"(b)); return r;
}
__device__ __forceinline__ float ex2f(float x) {
    float r; asm("ex2.approx.ftz.f32 %0, %1;" : "=f"(r) : "f"(x)); return r;
}

// ---------------------------------------------------------------------------
// Kernel 1: projection.  dst[n][e] = sum_i w[e][i] * Q[i][n]
// Grid (391 n-tiles, 4 = {mat} x {e-half}). Block 128 = 4 warps.
// Packing along NODE pairs: q2 = (Q[i][n], Q[i][n+1]) is a natural float2
// gmem load; weights duplicated (w,w) in smem so one LDS.128 feeds 2 e's.
// Thread = 2 n-pairs x 8 e  ->  per i-step: 2 LDG.64 + 4 LDS.128 + 16 fma2.
// ---------------------------------------------------------------------------
__global__ __launch_bounds__(128) void proj_kernel(
    const float* __restrict__ Q,      // [IN_F][N_NODES]
    const float* __restrict__ qw,     // [EDIM][IN_F]
    const float* __restrict__ kw)     // [EDIM][IN_F]
{
    __shared__ ull   sWd[IN_F][32];       // [i][e_local] dup pairs, 16 KB
    __shared__ float sS[PT_NODES][33];    // 16.9 KB staging, 2-way-max banks

    const int   mat = blockIdx.y >> 1;
    const int   eh  = (blockIdx.y & 1) * 32;          // e offset (0/32)
    const float* w  = mat ? kw : qw;
    float*      dst = mat ? g_Kf : g_Qf;

    // Load + duplicate my 32 e-rows of weights.
    for (int t = threadIdx.x; t < IN_F * 32; t += 128) {
        int i = t >> 5, el = t & 31;
        float v = w[(eh + el) * IN_F + i];
        sWd[i][el] = pack2(v, v);
    }
    __syncthreads();

    const int warp = threadIdx.x >> 5;
    const int lane = threadIdx.x & 31;
    const int es   = warp * 8;                        // my 8 e_locals
    const int n0   = blockIdx.x * PT_NODES;
    const int nA   = min(n0 + 2 * lane,      N_NODES - 2);  // pair A
    const int nB   = min(n0 + 64 + 2 * lane, N_NODES - 2);  // pair B

    ull acc[2][8];
#pragma unroll
    for (int p = 0; p < 2; p++)
#pragma unroll
        for (int e = 0; e < 8; e++) acc[p][e] = 0ull;

#pragma unroll 8
    for (int i = 0; i < IN_F; i++) {
        float2 a2 = *reinterpret_cast<const float2*>(&Q[i * N_NODES + nA]);
        float2 b2 = *reinterpret_cast<const float2*>(&Q[i * N_NODES + nB]);
        ull qA = pack2(a2.x, a2.y);
        ull qB = pack2(b2.x, b2.y);
        const ulonglong2* wr = reinterpret_cast<const ulonglong2*>(&sWd[i][es]);
        ulonglong2 w01 = wr[0], w23 = wr[1], w45 = wr[2], w67 = wr[3];
        fma2(acc[0][0], w01.x, qA); fma2(acc[1][0], w01.x, qB);
        fma2(acc[0][1], w01.y, qA); fma2(acc[1][1], w01.y, qB);
        fma2(acc[0][2], w23.x, qA); fma2(acc[1][2], w23.x, qB);
        fma2(acc[0][3], w23.y, qA); fma2(acc[1][3], w23.y, qB);
        fma2(acc[0][4], w45.x, qA); fma2(acc[1][4], w45.x, qB);
        fma2(acc[0][5], w45.y, qA); fma2(acc[1][5], w45.y, qB);
        fma2(acc[0][6], w67.x, qA); fma2(acc[1][6], w67.x, qB);
        fma2(acc[0][7], w67.y, qA); fma2(acc[1][7], w67.y, qB);
    }

    // Stage to SMEM (un-pack node pairs into rows).
#pragma unroll
    for (int e = 0; e < 8; e++) {
        float2 vA = unpack2(acc[0][e]);
        float2 vB = unpack2(acc[1][e]);
        sS[2 * lane + 0][es + e]      = vA.x;
        sS[2 * lane + 1][es + e]      = vA.y;
        sS[64 + 2 * lane + 0][es + e] = vB.x;
        sS[64 + 2 * lane + 1][es + e] = vB.y;
    }
    __syncthreads();

    // Coalesced store: 32 consecutive e per node (128B runs).
    const int nmax = min(PT_NODES, N_NODES - n0);
    for (int idx = threadIdx.x; idx < nmax * 32; idx += 128) {
        int nl = idx >> 5, el = idx & 31;
        dst[(n0 + nl) * EDIM + eh + el] = sS[nl][el];
    }
}

// ---------------------------------------------------------------------------
// Kernel 2: gather + attention + aggregate. R5/R7 layout (wf-optimal):
// warp per node, half = lane>>4 handles neighbor 2t+half, lane owns float4
// at foff=(lane&15)*4. Max-free softmax in exp2 domain; lrelu folded into
// the dot via |x|.
// NEW: all 16 neighbor indices hoisted (jks[]) and the gather load made
// unconditional on a clamped row — all addresses live at loop entry, no
// predication: the compiler can keep 4-6 LDGs in flight (latency hiding).
// Pads stay exact: their softmax weight e is forced to 0.
// ---------------------------------------------------------------------------
__global__ __launch_bounds__(256) void gat_kernel(
    const int*   __restrict__ adj,    // [N_NODES][DEG]
    const float* __restrict__ aw,     // [EDIM]
    float*       __restrict__ out)    // [EDIM][N_NODES]
{
    const unsigned FULL = 0xffffffffu;
    const float LOG2E = 1.4426950408889634f;
    const int warp = threadIdx.x >> 5;
    const int lane = threadIdx.x & 31;
    const int half = lane >> 4;
    const int foff = (lane & 15) * 4;
    const int n = blockIdx.x * 8 + warp;          // grid exact: 6250*8 = 50000

    __shared__ float sOut[EDIM][9];               // pitch 9 to spread banks

    int j = adj[n * DEG + lane];
    // hoist all neighbor indices for my half out of the loop
    int jks[DEG / 2];
#pragma unroll
    for (int t = 0; t < DEG / 2; t++)
        jks[t] = __shfl_sync(FULL, j, (t << 1) | half);

    ulonglong2 qp = *reinterpret_cast<const ulonglong2*>(&g_Qf[n * EDIM + foff]);
    float4 w4 = *reinterpret_cast<const float4*>(&aw[foff]);
    // lrelu(x) = 0.505x + 0.495|x| (slope 0.01); fold log2(e) for exp2 domain
    const float c1 = 0.505f * LOG2E, c2 = 0.495f * LOG2E;
    float w1x = w4.x * c1, w1y = w4.y * c1, w1z = w4.z * c1, w1w = w4.w * c1;
    float w2x = w4.x * c2, w2y = w4.y * c2, w2z = w4.z * c2, w2w = w4.w * c2;

    float s = 0.f;
    ull accA = 0ull, accB = 0ull;

#pragma unroll
    for (int t = 0; t < DEG / 2; t++) {
        int jk  = jks[t];
        int row = max(jk, 0);                     // clamp: load unconditionally
        ulonglong2 kp =
            *reinterpret_cast<const ulonglong2*>(&g_Kf[row * EDIM + foff]);

        // x = q + k (packed), dot with split weights (|x| folds into FFMA)
        float2 xa = unpack2(add2(qp.x, kp.x));
        float2 xb = unpack2(add2(qp.y, kp.y));
        float p1, p2;
        p1 = w1x * xa.x;             p2 = w2x * fabsf(xa.x);
        p1 = fmaf(w1y, xa.y, p1);    p2 = fmaf(w2y, fabsf(xa.y), p2);
        p1 = fmaf(w1z, xb.x, p1);    p2 = fmaf(w2z, fabsf(xb.x), p2);
        p1 = fmaf(w1w, xb.y, p1);    p2 = fmaf(w2w, fabsf(xb.y), p2);
        float p = p1 + p2;

        // reduce over 16 out-features of this head (4 lanes x 4 feats)
        p += __shfl_xor_sync(FULL, p, 1);
        p += __shfl_xor_sync(FULL, p, 2);

        // max-free softmax term; padded edge -> weight 0 (kills garbage kf too)
        float e = (jk >= 0) ? ex2f(p) : 0.f;
        s += e;
        ull e2 = pack2(e, e);
        fma2(accA, e2, kp.x);
        fma2(accB, e2, kp.y);
    }

    // merge the two halves (even/odd neighbors); same features at lane^16
    float2 A = unpack2(accA), B = unpack2(accB);
    s   += __shfl_xor_sync(FULL, s, 16);
    A.x += __shfl_xor_sync(FULL, A.x, 16);
    A.y += __shfl_xor_sync(FULL, A.y, 16);
    B.x += __shfl_xor_sync(FULL, B.x, 16);
    B.y += __shfl_xor_sync(FULL, B.y, 16);

    // all-pad rows: s == 0, acc == 0 -> output exactly 0 (matches reference)
    float inv = __frcp_rn(fmaxf(s, 1e-30f));
    if (half == 0) {
        sOut[foff + 0][warp] = A.x * inv;
        sOut[foff + 1][warp] = A.y * inv;
        sOut[foff + 2][warp] = B.x * inv;
        sOut[foff + 3][warp] = B.y * inv;
    }
    __syncthreads();

    // Coalesced store: 512 elements, 8 consecutive n per feature row.
    const int n0 = blockIdx.x * 8;
#pragma unroll
    for (int idx = threadIdx.x; idx < EDIM * 8; idx += 256) {
        int e  = idx >> 3;
        int nn = idx & 7;
        out[e * N_NODES + n0 + nn] = sOut[e][nn];
    }
}

// ---------------------------------------------------------------------------
extern "C" void kernel_launch(void* const* d_in, const int* in_sizes, int n_in,
                              void* d_out, int out_size)
{
    const int*   adj = (const int*)  d_in[0];   // [50000*32] int32
    const float* Q   = (const float*)d_in[1];   // [64*50000]
    const float* qw  = (const float*)d_in[2];   // [4*16*64]
    const float* kw  = (const float*)d_in[3];   // [4*16*64]
    const float* aw  = (const float*)d_in[4];   // [4*16]
    float* out = (float*)d_out;                 // [4*16*50000]

    (void)in_sizes; (void)n_in; (void)out_size;

    dim3 pgrid((N_NODES + PT_NODES - 1) / PT_NODES, 4);   // 391 x 4
    proj_kernel<<<pgrid, 128>>>(Q, qw, kw);
    gat_kernel<<<N_NODES / 8, 256>>>(adj, aw, out);
}

// round 9
// speedup vs baseline: 1.3561x; 1.3561x over previous
#include <cuda_runtime.h>
#include <cuda_bf16.h>
#include <cstdint>

#define N_NODES 50000
#define DEG     32
#define HEADS   4
#define OUT_F   16
#define IN_F    64
#define EDIM    (HEADS * OUT_F)   // 64 combined (h,o) features
#define PT_NODES 64               // nodes per proj block

typedef unsigned long long ull;

// Scratch: projected queries/keys, node-major (256B contiguous per node).
__device__ __align__(16) float g_Qf[N_NODES * EDIM];
__device__ __align__(16) float g_Kf[N_NODES * EDIM];

// ---------------------------------------------------------------------------
// helpers
// ---------------------------------------------------------------------------
__device__ __forceinline__ ull pack2(float a, float b) {
    ull r; asm("mov.b64 %0, {%1, %2};" : "=l"(r) : "f"(a), "f"(b)); return r;
}
__device__ __forceinline__ float2 unpack2(ull v) {
    float2 r; asm("mov.b64 {%0, %1}, %2;" : "=f"(r.x), "=f"(r.y) : "l"(v)); return r;
}
__device__ __forceinline__ void fma2(ull& d, ull a, ull b) {
    asm("fma.rn.f32x2 %0, %1, %2, %0;" : "+l"(d) : "l"(a), "l"(b));
}
__device__ __forceinline__ ull add2(ull a, ull b) {
    ull r; asm("add.rn.f32x2 %0, %1, %2;" : "=l"(r) : "l"(a), "l"(b)); return r;
}
__device__ __forceinline__ float ex2f(float x) {
    float r; asm("ex2.approx.ftz.f32 %0, %1;" : "=f"(r) : "f"(x)); return r;
}
__device__ __forceinline__ uint32_t pbf2(float x, float y) {
    __nv_bfloat162 h = __floats2bfloat162_rn(x, y);
    return *reinterpret_cast<uint32_t*>(&h);
}
__device__ __forceinline__ void mma_bf16(float* d, const uint32_t* a,
                                         uint32_t b0, uint32_t b1) {
    asm("mma.sync.aligned.m16n8k16.row.col.f32.bf16.bf16.f32 "
        "{%0,%1,%2,%3}, {%4,%5,%6,%7}, {%8,%9}, {%0,%1,%2,%3};"
        : "+f"(d[0]), "+f"(d[1]), "+f"(d[2]), "+f"(d[3])
        : "r"(a[0]), "r"(a[1]), "r"(a[2]), "r"(a[3]), "r"(b0), "r"(b1));
}

// ---------------------------------------------------------------------------
// Kernel 1: projection on TENSOR CORES.
//   D[128 x 64nodes] = Wstk[128 x 64] * Qtile[64 x 64nodes]
// where Wstk = [qw ; kw] stacked on M. Split-bf16 (hi+lo), 3-term MMA:
// D = Ah*Bh + Al*Bh + Ah*Bl  (error ~1e-5 rel; lo*lo term dropped).
// Block 256 thr = 8 warps; warp w owns M-rows [16w,16w+16) (w<4: qw, else kw).
// B smem pitch 72 bf16 (36 words == 4 mod 32) -> conflict-free frag loads.
// ---------------------------------------------------------------------------
#define BPITCH 72   // bf16 elems per B smem row
#define SPITCH 130  // floats per sS row

__global__ __launch_bounds__(256) void proj_kernel(
    const float* __restrict__ Q,      // [IN_F][N_NODES]
    const float* __restrict__ qw,     // [EDIM][IN_F]
    const float* __restrict__ kw)     // [EDIM][IN_F]
{
    __shared__ __nv_bfloat16 Bh[PT_NODES * BPITCH];  // 9.2 KB
    __shared__ __nv_bfloat16 Bl[PT_NODES * BPITCH];  // 9.2 KB
    __shared__ float         sS[PT_NODES * SPITCH];  // 33.3 KB

    const int tid  = threadIdx.x;
    const int warp = tid >> 5;
    const int lane = tid & 31;
    const int g    = lane >> 2;       // groupID
    const int t    = lane & 3;        // threadID in group
    const int n0   = blockIdx.x * PT_NODES;

    // ---- A fragments (weights), hi/lo split, straight from gmem ----
    const float* W = (warp < 4) ? qw : kw;
    const int er   = (warp & 3) * 16 + g;    // my e-row (and er+8)
    uint32_t ah[4][4], al[4][4];
#pragma unroll
    for (int kt = 0; kt < 4; kt++) {
        float2 p00 = *reinterpret_cast<const float2*>(&W[er * 64 + kt * 16 + 2 * t]);
        float2 p10 = *reinterpret_cast<const float2*>(&W[(er + 8) * 64 + kt * 16 + 2 * t]);
        float2 p01 = *reinterpret_cast<const float2*>(&W[er * 64 + kt * 16 + 8 + 2 * t]);
        float2 p11 = *reinterpret_cast<const float2*>(&W[(er + 8) * 64 + kt * 16 + 8 + 2 * t]);
        float h;
#define SPLIT(reg_h, reg_l, v)                                              \
        {                                                                   \
            float hx, hy;                                                   \
            hx = __bfloat162float(__float2bfloat16_rn((v).x));              \
            hy = __bfloat162float(__float2bfloat16_rn((v).y));              \
            reg_h = pbf2(hx, hy);                                           \
            reg_l = pbf2((v).x - hx, (v).y - hy);                           \
        }
        SPLIT(ah[kt][0], al[kt][0], p00);
        SPLIT(ah[kt][1], al[kt][1], p10);
        SPLIT(ah[kt][2], al[kt][2], p01);
        SPLIT(ah[kt][3], al[kt][3], p11);
        (void)h;
    }

    // ---- Q tile: fp32 -> (hi, lo) bf16 pairs in smem ----
    // pair index p = i/2 (32 pairs), node n (64): Bh32[n*36 + p] = (bf16 i=2p, 2p+1)
    uint32_t* Bh32 = reinterpret_cast<uint32_t*>(Bh);
    uint32_t* Bl32 = reinterpret_cast<uint32_t*>(Bl);
#pragma unroll
    for (int r = 0; r < 8; r++) {
        int e2 = tid + 256 * r;                 // 2048 pairs
        int n  = e2 & 63;
        int p  = e2 >> 6;                       // 0..31
        int nn = min(n0 + n, N_NODES - 1);
        float x0 = Q[(2 * p + 0) * N_NODES + nn];
        float x1 = Q[(2 * p + 1) * N_NODES + nn];
        float h0 = __bfloat162float(__float2bfloat16_rn(x0));
        float h1 = __bfloat162float(__float2bfloat16_rn(x1));
        Bh32[n * (BPITCH / 2) + p] = pbf2(h0, h1);
        Bl32[n * (BPITCH / 2) + p] = pbf2(x0 - h0, x1 - h1);
    }
    __syncthreads();

    // ---- MMA mainloop: 8 n-tiles x 4 k-tiles x 3 terms ----
#pragma unroll
    for (int nt = 0; nt < 8; nt++) {
        float d[4] = {0.f, 0.f, 0.f, 0.f};
#pragma unroll
        for (int kt = 0; kt < 4; kt++) {
            int boff = (nt * 8 + g) * BPITCH + kt * 16 + 2 * t;
            uint32_t bh0 = *reinterpret_cast<const uint32_t*>(&Bh[boff]);
            uint32_t bh1 = *reinterpret_cast<const uint32_t*>(&Bh[boff + 8]);
            uint32_t bl0 = *reinterpret_cast<const uint32_t*>(&Bl[boff]);
            uint32_t bl1 = *reinterpret_cast<const uint32_t*>(&Bl[boff + 8]);
            mma_bf16(d, ah[kt], bh0, bh1);   // hi*hi
            mma_bf16(d, al[kt], bh0, bh1);   // lo*hi
            mma_bf16(d, ah[kt], bl0, bl1);   // hi*lo
        }
        // D frag: rows er (c0,c1), er+8 (c2,c3); cols n = nt*8 + 2t (+1)
        int col0 = er + ((warp >= 4) ? 64 : 0);
        int nl   = nt * 8 + 2 * t;
        sS[nl * SPITCH + col0]           = d[0];
        sS[(nl + 1) * SPITCH + col0]     = d[1];
        sS[nl * SPITCH + col0 + 8]       = d[2];
        sS[(nl + 1) * SPITCH + col0 + 8] = d[3];
    }
    __syncthreads();

    // ---- coalesced store: cols 0-63 -> g_Qf, 64-127 -> g_Kf ----
    const int nmax = min(PT_NODES, N_NODES - n0);
    for (int idx = tid; idx < nmax * 128; idx += 256) {
        int n = idx >> 7, c = idx & 127;
        float v = sS[n * SPITCH + c];
        if (c < 64) g_Qf[(n0 + n) * EDIM + c]        = v;
        else        g_Kf[(n0 + n) * EDIM + (c - 64)] = v;
    }
}

// ---------------------------------------------------------------------------
// Kernel 2: gather + attention + aggregate (unchanged from R8 best: 38.7us).
// Warp per node, half = lane>>4 handles neighbor 2t+half, lane owns float4 at
// foff=(lane&15)*4. Hoisted neighbor indices + unconditional clamped loads;
// max-free softmax in exp2 domain; lrelu folded into the dot via |x|.
// ---------------------------------------------------------------------------
__global__ __launch_bounds__(256) void gat_kernel(
    const int*   __restrict__ adj,    // [N_NODES][DEG]
    const float* __restrict__ aw,     // [EDIM]
    float*       __restrict__ out)    // [EDIM][N_NODES]
{
    const unsigned FULL = 0xffffffffu;
    const float LOG2E = 1.4426950408889634f;
    const int warp = threadIdx.x >> 5;
    const int lane = threadIdx.x & 31;
    const int half = lane >> 4;
    const int foff = (lane & 15) * 4;
    const int n = blockIdx.x * 8 + warp;          // grid exact: 6250*8 = 50000

    __shared__ float sOut[EDIM][9];               // pitch 9 to spread banks

    int j = adj[n * DEG + lane];
    int jks[DEG / 2];
#pragma unroll
    for (int t = 0; t < DEG / 2; t++)
        jks[t] = __shfl_sync(FULL, j, (t << 1) | half);

    ulonglong2 qp = *reinterpret_cast<const ulonglong2*>(&g_Qf[n * EDIM + foff]);
    float4 w4 = *reinterpret_cast<const float4*>(&aw[foff]);
    const float c1 = 0.505f * LOG2E, c2 = 0.495f * LOG2E;
    float w1x = w4.x * c1, w1y = w4.y * c1, w1z = w4.z * c1, w1w = w4.w * c1;
    float w2x = w4.x * c2, w2y = w4.y * c2, w2z = w4.z * c2, w2w = w4.w * c2;

    float s = 0.f;
    ull accA = 0ull, accB = 0ull;

#pragma unroll
    for (int t = 0; t < DEG / 2; t++) {
        int jk  = jks[t];
        int row = max(jk, 0);                     // clamp: load unconditionally
        ulonglong2 kp =
            *reinterpret_cast<const ulonglong2*>(&g_Kf[row * EDIM + foff]);

        float2 xa = unpack2(add2(qp.x, kp.x));
        float2 xb = unpack2(add2(qp.y, kp.y));
        float p1, p2;
        p1 = w1x * xa.x;             p2 = w2x * fabsf(xa.x);
        p1 = fmaf(w1y, xa.y, p1);    p2 = fmaf(w2y, fabsf(xa.y), p2);
        p1 = fmaf(w1z, xb.x, p1);    p2 = fmaf(w2z, fabsf(xb.x), p2);
        p1 = fmaf(w1w, xb.y, p1);    p2 = fmaf(w2w, fabsf(xb.y), p2);
        float p = p1 + p2;

        p += __shfl_xor_sync(FULL, p, 1);
        p += __shfl_xor_sync(FULL, p, 2);

        float e = (jk >= 0) ? ex2f(p) : 0.f;      // pad -> weight 0
        s += e;
        ull e2 = pack2(e, e);
        fma2(accA, e2, kp.x);
        fma2(accB, e2, kp.y);
    }

    float2 A = unpack2(accA), B = unpack2(accB);
    s   += __shfl_xor_sync(FULL, s, 16);
    A.x += __shfl_xor_sync(FULL, A.x, 16);
    A.y += __shfl_xor_sync(FULL, A.y, 16);
    B.x += __shfl_xor_sync(FULL, B.x, 16);
    B.y += __shfl_xor_sync(FULL, B.y, 16);

    float inv = __frcp_rn(fmaxf(s, 1e-30f));
    if (half == 0) {
        sOut[foff + 0][warp] = A.x * inv;
        sOut[foff + 1][warp] = A.y * inv;
        sOut[foff + 2][warp] = B.x * inv;
        sOut[foff + 3][warp] = B.y * inv;
    }
    __syncthreads();

    const int n0 = blockIdx.x * 8;
#pragma unroll
    for (int idx = threadIdx.x; idx < EDIM * 8; idx += 256) {
        int e  = idx >> 3;
        int nn = idx & 7;
        out[e * N_NODES + n0 + nn] = sOut[e][nn];
    }
}

// ---------------------------------------------------------------------------
extern "C" void kernel_launch(void* const* d_in, const int* in_sizes, int n_in,
                              void* d_out, int out_size)
{
    const int*   adj = (const int*)  d_in[0];   // [50000*32] int32
    const float* Q   = (const float*)d_in[1];   // [64*50000]
    const float* qw  = (const float*)d_in[2];   // [4*16*64]
    const float* kw  = (const float*)d_in[3];   // [4*16*64]
    const float* aw  = (const float*)d_in[4];   // [4*16]
    float* out = (float*)d_out;                 // [4*16*50000]

    (void)in_sizes; (void)n_in; (void)out_size;

    proj_kernel<<<(N_NODES + PT_NODES - 1) / PT_NODES, 256>>>(Q, qw, kw);
    gat_kernel<<<N_NODES / 8, 256>>>(adj, aw, out);
}